// round 1
// baseline (speedup 1.0000x reference)
#include <cuda_runtime.h>

#define DM 1024
#define NH 16
#define DKH 64
#define BB 2
#define SS 2048
#define MTOT (BB*SS)

// ---------------- scratch (static device arrays: allocation-free) ----------
__device__ float g_Q[MTOT*DM];   // [B,H,S,dk]
__device__ float g_K[MTOT*DM];   // [B,H,S,dk]
__device__ float g_V[MTOT*DM];   // [B,H,S,dk]
__device__ float g_A[MTOT*DM];   // [B,S,D] attention output (concat heads)

// ---------------- shared 64x64x16 GEMM micro-kernel body -------------------
// C[m][n] = sum_k A[m][k] * W[n][k]   (both operands K-major row-major)
__device__ __forceinline__ void gemm_body(const float* __restrict__ Ap,
                                          const float* __restrict__ Wp,
                                          int m0, int n0, float acc[4][4]) {
    __shared__ float As[16][64];   // [k][m] transposed
    __shared__ float Ws[16][64];   // [k][n] transposed
    const int tid = threadIdx.x;
    const int tx = tid & 15, ty = tid >> 4;
    const int lm = tid >> 2;
    const int lk = (tid & 3) << 2;
    const float* Ag = Ap + (size_t)(m0 + lm) * DM + lk;
    const float* Wg = Wp + (size_t)(n0 + lm) * DM + lk;

    for (int k0 = 0; k0 < DM; k0 += 16) {
        float4 a = *(const float4*)(Ag + k0);
        float4 w = *(const float4*)(Wg + k0);
        __syncthreads();
        As[lk+0][lm] = a.x; As[lk+1][lm] = a.y; As[lk+2][lm] = a.z; As[lk+3][lm] = a.w;
        Ws[lk+0][lm] = w.x; Ws[lk+1][lm] = w.y; Ws[lk+2][lm] = w.z; Ws[lk+3][lm] = w.w;
        __syncthreads();
#pragma unroll
        for (int kk = 0; kk < 16; kk++) {
            float4 av = *(const float4*)&As[kk][ty*4];
            float4 wv = *(const float4*)&Ws[kk][tx*4];
            acc[0][0] += av.x*wv.x; acc[0][1] += av.x*wv.y; acc[0][2] += av.x*wv.z; acc[0][3] += av.x*wv.w;
            acc[1][0] += av.y*wv.x; acc[1][1] += av.y*wv.y; acc[1][2] += av.y*wv.z; acc[1][3] += av.y*wv.w;
            acc[2][0] += av.z*wv.x; acc[2][1] += av.z*wv.y; acc[2][2] += av.z*wv.z; acc[2][3] += av.z*wv.w;
            acc[3][0] += av.w*wv.x; acc[3][1] += av.w*wv.y; acc[3][2] += av.w*wv.z; acc[3][3] += av.w*wv.w;
        }
    }
}

// ---------------- kernel 1: fused Q/K/V projections ------------------------
// grid: (DM/64, MTOT/64, 3). Stores into per-head layout [B,H,S,dk].
__global__ __launch_bounds__(256)
void proj_kernel(const float* __restrict__ x,
                 const float* __restrict__ Wq,
                 const float* __restrict__ Wk,
                 const float* __restrict__ Wv) {
    const float* W = (blockIdx.z == 0) ? Wq : (blockIdx.z == 1) ? Wk : Wv;
    float* C       = (blockIdx.z == 0) ? g_Q : (blockIdx.z == 1) ? g_K : g_V;
    const int n0 = blockIdx.x * 64;
    const int m0 = blockIdx.y * 64;
    float acc[4][4] = {};
    gemm_body(x, W, m0, n0, acc);

    const int tx = threadIdx.x & 15, ty = threadIdx.x >> 4;
    const int h = n0 >> 6;          // n-tile aligns exactly with one head
#pragma unroll
    for (int i = 0; i < 4; i++) {
        int m = m0 + ty*4 + i;
        int b = m >> 11;            // m / SS
        int s = m & (SS - 1);
        float4 v = make_float4(acc[i][0], acc[i][1], acc[i][2], acc[i][3]);
        *(float4*)(C + ((size_t)((b*NH + h)*SS + s))*DKH + tx*4) = v;
    }
}

// ---------------- kernel 2: causal flash attention -------------------------
// grid: (SS/64, NH, BB), block 256. Dynamic smem = 4*64*68 + 192 floats.
#define SMEM_FLASH ((4*64*68 + 192) * 4)

__global__ __launch_bounds__(256)
void flash_kernel() {
    extern __shared__ float sm[];
    float* Qt    = sm;               // [d][q]  64x68
    float* Kt    = sm + 64*68;       // [d][k]  64x68
    float* Vs    = sm + 2*64*68;     // [k][d]  64x68
    float* Ps    = sm + 3*64*68;     // [q][k]  64x68
    float* rowm  = sm + 4*64*68;     // [64]
    float* rowl  = rowm + 64;        // [64]
    float* ralpha= rowl + 64;        // [64]

    const int tid = threadIdx.x;
    const int tx = tid & 15, ty = tid >> 4;
    const int qt = blockIdx.x, h = blockIdx.y, b = blockIdx.z;
    const int q0 = qt * 64;

    const float* Qg = g_Q + ((size_t)(b*NH + h)*SS + q0) * DKH;
    const float* Kg = g_K + ((size_t)(b*NH + h)*SS) * DKH;
    const float* Vg = g_V + ((size_t)(b*NH + h)*SS) * DKH;

    // load Q tile transposed: Qt[d][q]
#pragma unroll
    for (int r = 0; r < 4; r++) {
        int e = tid + r*256;
        int qq = e >> 4;
        int d4 = (e & 15) << 2;
        float4 v = *(const float4*)(Qg + qq*DKH + d4);
        Qt[(d4+0)*68 + qq] = v.x; Qt[(d4+1)*68 + qq] = v.y;
        Qt[(d4+2)*68 + qq] = v.z; Qt[(d4+3)*68 + qq] = v.w;
    }
    if (tid < 64) { rowm[tid] = -1e30f; rowl[tid] = 0.0f; }

    float o[4][4] = {};

    for (int kt = 0; kt <= qt; kt++) {
        const int k0 = kt * 64;
        __syncthreads();   // previous PV done / first-iter Q+init visible
        // load K transposed, V direct
#pragma unroll
        for (int r = 0; r < 4; r++) {
            int e = tid + r*256;
            int kk = e >> 4;
            int d4 = (e & 15) << 2;
            float4 kv = *(const float4*)(Kg + (size_t)(k0+kk)*DKH + d4);
            Kt[(d4+0)*68 + kk] = kv.x; Kt[(d4+1)*68 + kk] = kv.y;
            Kt[(d4+2)*68 + kk] = kv.z; Kt[(d4+3)*68 + kk] = kv.w;
            float4 vv = *(const float4*)(Vg + (size_t)(k0+kk)*DKH + d4);
            *(float4*)&Vs[kk*68 + d4] = vv;
        }
        __syncthreads();

        // S = Q @ K^T (64x64x64)
        float s[4][4] = {};
#pragma unroll 8
        for (int d = 0; d < 64; d++) {
            float4 qv = *(const float4*)&Qt[d*68 + ty*4];
            float4 kv = *(const float4*)&Kt[d*68 + tx*4];
            s[0][0] += qv.x*kv.x; s[0][1] += qv.x*kv.y; s[0][2] += qv.x*kv.z; s[0][3] += qv.x*kv.w;
            s[1][0] += qv.y*kv.x; s[1][1] += qv.y*kv.y; s[1][2] += qv.y*kv.z; s[1][3] += qv.y*kv.w;
            s[2][0] += qv.z*kv.x; s[2][1] += qv.z*kv.y; s[2][2] += qv.z*kv.z; s[2][3] += qv.z*kv.w;
            s[3][0] += qv.w*kv.x; s[3][1] += qv.w*kv.y; s[3][2] += qv.w*kv.z; s[3][3] += qv.w*kv.w;
        }
        // scale + causal mask + stage to Ps
#pragma unroll
        for (int i = 0; i < 4; i++) {
            int qg = q0 + ty*4 + i;
            float4 pv;
            pv.x = s[i][0]*0.125f + ((k0 + tx*4 + 0) > qg ? -1e9f : 0.0f);
            pv.y = s[i][1]*0.125f + ((k0 + tx*4 + 1) > qg ? -1e9f : 0.0f);
            pv.z = s[i][2]*0.125f + ((k0 + tx*4 + 2) > qg ? -1e9f : 0.0f);
            pv.w = s[i][3]*0.125f + ((k0 + tx*4 + 3) > qg ? -1e9f : 0.0f);
            *(float4*)&Ps[(ty*4+i)*68 + tx*4] = pv;
        }
        __syncthreads();

        // online softmax: one thread per row
        if (tid < 64) {
            int row = tid;
            float* pr = &Ps[row*68];
            float mo = rowm[row];
            float mx = mo;
#pragma unroll 8
            for (int j = 0; j < 64; j++) mx = fmaxf(mx, pr[j]);
            float a = __expf(mo - mx);
            float sum = 0.0f;
#pragma unroll 8
            for (int j = 0; j < 64; j++) { float p = __expf(pr[j] - mx); pr[j] = p; sum += p; }
            rowl[row] = rowl[row]*a + sum;
            rowm[row] = mx;
            ralpha[row] = a;
        }
        __syncthreads();

        // O = O*alpha + P @ V
#pragma unroll
        for (int i = 0; i < 4; i++) {
            float a = ralpha[ty*4 + i];
            o[i][0]*=a; o[i][1]*=a; o[i][2]*=a; o[i][3]*=a;
        }
#pragma unroll 8
        for (int kk = 0; kk < 64; kk++) {
            float4 vv = *(const float4*)&Vs[kk*68 + tx*4];
            float p0 = Ps[(ty*4+0)*68 + kk];
            float p1 = Ps[(ty*4+1)*68 + kk];
            float p2 = Ps[(ty*4+2)*68 + kk];
            float p3 = Ps[(ty*4+3)*68 + kk];
            o[0][0]+=p0*vv.x; o[0][1]+=p0*vv.y; o[0][2]+=p0*vv.z; o[0][3]+=p0*vv.w;
            o[1][0]+=p1*vv.x; o[1][1]+=p1*vv.y; o[1][2]+=p1*vv.z; o[1][3]+=p1*vv.w;
            o[2][0]+=p2*vv.x; o[2][1]+=p2*vv.y; o[2][2]+=p2*vv.z; o[2][3]+=p2*vv.w;
            o[3][0]+=p3*vv.x; o[3][1]+=p3*vv.y; o[3][2]+=p3*vv.z; o[3][3]+=p3*vv.w;
        }
    }

    // finalize: divide by l, write concat-head layout [B,S,D]
#pragma unroll
    for (int i = 0; i < 4; i++) {
        int row = ty*4 + i;
        float inv = 1.0f / rowl[row];
        float4 ov = make_float4(o[i][0]*inv, o[i][1]*inv, o[i][2]*inv, o[i][3]*inv);
        int q = q0 + row;
        *(float4*)(g_A + ((size_t)(b*SS + q))*DM + h*DKH + tx*4) = ov;
    }
}

// ---------------- kernel 3: output projection ------------------------------
__global__ __launch_bounds__(256)
void outproj_kernel(const float* __restrict__ Wo, float* __restrict__ C) {
    const int n0 = blockIdx.x * 64;
    const int m0 = blockIdx.y * 64;
    float acc[4][4] = {};
    gemm_body(g_A, Wo, m0, n0, acc);
    const int tx = threadIdx.x & 15, ty = threadIdx.x >> 4;
#pragma unroll
    for (int i = 0; i < 4; i++) {
        float4 v = make_float4(acc[i][0], acc[i][1], acc[i][2], acc[i][3]);
        *(float4*)(C + (size_t)(m0 + ty*4 + i)*DM + n0 + tx*4) = v;
    }
}

// ---------------- launch ----------------------------------------------------
extern "C" void kernel_launch(void* const* d_in, const int* in_sizes, int n_in,
                              void* d_out, int out_size) {
    const float* x  = (const float*)d_in[0];
    // d_in[1] is the additive causal mask; mask is computed analytically in-kernel.
    const float* Wq = (const float*)d_in[2];
    const float* Wk = (const float*)d_in[3];
    const float* Wv = (const float*)d_in[4];
    const float* Wo = (const float*)d_in[5];
    float* out = (float*)d_out;

    dim3 gproj(DM/64, MTOT/64, 3);
    proj_kernel<<<gproj, 256>>>(x, Wq, Wk, Wv);

    cudaFuncSetAttribute(flash_kernel, cudaFuncAttributeMaxDynamicSharedMemorySize, SMEM_FLASH);
    dim3 gflash(SS/64, NH, BB);
    flash_kernel<<<gflash, 256, SMEM_FLASH>>>();

    dim3 gout(DM/64, MTOT/64, 1);
    outproj_kernel<<<gout, 256>>>(Wo, out);
}

// round 4
// speedup vs baseline: 1.5602x; 1.5602x over previous
#include <cuda_runtime.h>
#include <cuda_bf16.h>
#include <cstdint>

#define DM 1024
#define NH 16
#define DKH 64
#define BB 2
#define SS 2048
#define MTOT (BB*SS)

// ---------------- scratch (static device arrays: allocation-free) ----------
__device__ float g_Q[MTOT*DM];   // [B,H,S,dk]
__device__ float g_K[MTOT*DM];
__device__ float g_V[MTOT*DM];
__device__ float g_A[MTOT*DM];   // [B,S,D] attention output
__device__ __nv_bfloat16 g_Xh[MTOT*DM], g_Xl[MTOT*DM];
__device__ __nv_bfloat16 g_Wh[4*DM*DM], g_Wl[4*DM*DM];
__device__ __nv_bfloat16 g_Ah[MTOT*DM], g_Al[MTOT*DM];

// ---------------- helpers ----------------------------------------------------
__device__ __forceinline__ uint32_t smem_u32(const void* p) {
    uint32_t a;
    asm("{ .reg .u64 t; cvta.to.shared.u64 t, %1; cvt.u32.u64 %0, t; }" : "=r"(a) : "l"(p));
    return a;
}
#define CP_ASYNC16(dst, src) \
    asm volatile("cp.async.cg.shared.global [%0], [%1], 16;" :: "r"(dst), "l"(src))
#define CP_COMMIT()  asm volatile("cp.async.commit_group;" ::: "memory")
#define CP_WAIT1()   asm volatile("cp.async.wait_group 1;" ::: "memory")
#define CP_WAIT0()   asm volatile("cp.async.wait_group 0;" ::: "memory")

#define LDMX4(r0, r1, r2, r3, addr) \
    asm volatile("ldmatrix.sync.aligned.m8n8.x4.shared.b16 {%0,%1,%2,%3}, [%4];" \
        : "=r"(r0), "=r"(r1), "=r"(r2), "=r"(r3) : "r"(addr))

#define MMA16816(d, a, b0, b1) \
    asm volatile("mma.sync.aligned.m16n8k16.row.col.f32.bf16.bf16.f32 " \
        "{%0,%1,%2,%3},{%4,%5,%6,%7},{%8,%9},{%0,%1,%2,%3};" \
        : "+f"((d)[0]), "+f"((d)[1]), "+f"((d)[2]), "+f"((d)[3]) \
        : "r"((a)[0]), "r"((a)[1]), "r"((a)[2]), "r"((a)[3]), "r"(b0), "r"(b1))

// ---------------- convert: fp32 -> bf16 hi/lo -------------------------------
// dst_sel: 0=X, 1..4=W[q,k,v,o], 5=A (src ignored, reads g_A)
__global__ __launch_bounds__(256)
void convert_kernel(const float* __restrict__ src, int dst_sel, int n4) {
    int i = blockIdx.x * 256 + threadIdx.x;
    if (i >= n4) return;
    __nv_bfloat16 *h, *l;
    if (dst_sel == 0)      { h = g_Xh; l = g_Xl; }
    else if (dst_sel <= 4) { size_t o = (size_t)(dst_sel - 1) * DM * DM; h = g_Wh + o; l = g_Wl + o; }
    else                   { h = g_Ah; l = g_Al; src = g_A; }
    float4 v = *(const float4*)(src + (size_t)i * 4);
    __nv_bfloat16 h0 = __float2bfloat16(v.x), h1 = __float2bfloat16(v.y),
                  h2 = __float2bfloat16(v.z), h3 = __float2bfloat16(v.w);
    __nv_bfloat16 l0 = __float2bfloat16(v.x - __bfloat162float(h0));
    __nv_bfloat16 l1 = __float2bfloat16(v.y - __bfloat162float(h1));
    __nv_bfloat16 l2 = __float2bfloat16(v.z - __bfloat162float(h2));
    __nv_bfloat16 l3 = __float2bfloat16(v.w - __bfloat162float(h3));
    __nv_bfloat162 hp0(h0, h1), hp1(h2, h3), lp0(l0, l1), lp1(l2, l3);
    *(uint2*)(h + (size_t)i * 4) = make_uint2(*(uint32_t*)&hp0, *(uint32_t*)&hp1);
    *(uint2*)(l + (size_t)i * 4) = make_uint2(*(uint32_t*)&lp0, *(uint32_t*)&lp1);
}

// ---------------- mma.sync bf16x3 GEMM --------------------------------------
// C[M,N] = A[M,K] @ B[N,K]^T; hi/lo split for fp32-equivalent precision.
#define TMM 128
#define TNN 128
#define KC 32
#define NCH (DM/KC)            // 32
#define ROWB 80                // 64B data + 16B pad (odd 16B phase -> low conflicts)
#define TILE_BYTES (128*ROWB)  // 10240
#define STAGE_BYTES (4*TILE_BYTES)
#define GEMM_SMEM (2*STAGE_BYTES)

__device__ __forceinline__ void load_chunk_async(uint32_t st,
        const __nv_bfloat16* Ah, const __nv_bfloat16* Al,
        const __nv_bfloat16* Bh, const __nv_bfloat16* Bl, int c, int tid) {
    const __nv_bfloat16* srcs[4] = { Ah, Al, Bh, Bl };
    const int q = tid & 3;            // 16B chunk within 64B row
    const int rh = tid >> 2;          // 0..63
#pragma unroll
    for (int t = 0; t < 4; t++) {
        const char* src = (const char*)(srcs[t] + (size_t)c * KC) + q * 16;
#pragma unroll
        for (int rr = 0; rr < 2; rr++) {
            int row = rh + rr * 64;
            uint32_t dst = st + t * TILE_BYTES + row * ROWB + q * 16;
            CP_ASYNC16(dst, src + (size_t)row * (DM * 2));
        }
    }
}

// mode 0: A = X (hi/lo), B = W[z], C = g_Q/g_K/g_V (per-head layout)
// mode 1: A = attn out (hi/lo), B = W[3], C = Cout ([B,S,D])
__global__ __launch_bounds__(256)
void tc_gemm_kernel(float* __restrict__ Cout, int mode) {
    extern __shared__ char smem[];
    const uint32_t sb = smem_u32(smem);
    const int tid = threadIdx.x, wid = tid >> 5, lane = tid & 31;
    const int n0 = blockIdx.x * TNN, m0 = blockIdx.y * TMM, z = blockIdx.z;

    const int widx = (mode == 0) ? z : 3;
    const __nv_bfloat16* Ah = ((mode == 0) ? g_Xh : g_Ah) + (size_t)m0 * DM;
    const __nv_bfloat16* Al = ((mode == 0) ? g_Xl : g_Al) + (size_t)m0 * DM;
    const __nv_bfloat16* Bh = g_Wh + (size_t)widx * DM * DM + (size_t)n0 * DM;
    const __nv_bfloat16* Bl = g_Wl + (size_t)widx * DM * DM + (size_t)n0 * DM;
    float* C = (mode == 0) ? (z == 0 ? g_Q : z == 1 ? g_K : g_V) : Cout;

    const int warp_m = (wid & 3) * 32;     // 4 warps over M
    const int warp_n = (wid >> 2) * 64;    // 2 warps over N

    float acc[2][8][4];
#pragma unroll
    for (int i = 0; i < 2; i++)
#pragma unroll
        for (int j = 0; j < 8; j++)
#pragma unroll
            for (int k = 0; k < 4; k++) acc[i][j][k] = 0.0f;

    load_chunk_async(sb, Ah, Al, Bh, Bl, 0, tid); CP_COMMIT();
    load_chunk_async(sb + STAGE_BYTES, Ah, Al, Bh, Bl, 1, tid); CP_COMMIT();

    // ldmatrix address components (lane-dependent)
    const int lrow = lane & 15;            // row within 16-row tile
    const int lcol = (lane >> 4) * 16;     // 0 or 16 bytes (k 0-7 / 8-15)

#pragma unroll 1
    for (int c = 0; c < NCH; c++) {
        CP_WAIT1();
        __syncthreads();
        const uint32_t st = sb + (uint32_t)(c & 1) * STAGE_BYTES;
        const uint32_t aH = st + (warp_m + lrow) * ROWB + lcol;
        const uint32_t aL = aH + TILE_BYTES;
        const uint32_t bH = st + 2 * TILE_BYTES + (warp_n + lrow) * ROWB + lcol;
        const uint32_t bL = bH + TILE_BYTES;

#pragma unroll
        for (int ks = 0; ks < 2; ks++) {
            const int kb = ks * 32;        // 16 bf16 = 32 bytes
            uint32_t ah[2][4], al[2][4];
#pragma unroll
            for (int mt = 0; mt < 2; mt++) {
                LDMX4(ah[mt][0], ah[mt][1], ah[mt][2], ah[mt][3], aH + mt * 16 * ROWB + kb);
                LDMX4(al[mt][0], al[mt][1], al[mt][2], al[mt][3], aL + mt * 16 * ROWB + kb);
            }
            uint32_t bh[4][4], bl[4][4];
#pragma unroll
            for (int bt = 0; bt < 4; bt++) {
                LDMX4(bh[bt][0], bh[bt][1], bh[bt][2], bh[bt][3], bH + bt * 16 * ROWB + kb);
                LDMX4(bl[bt][0], bl[bt][1], bl[bt][2], bl[bt][3], bL + bt * 16 * ROWB + kb);
            }
#pragma unroll
            for (int mt = 0; mt < 2; mt++) {
#pragma unroll
                for (int bt = 0; bt < 4; bt++) {
                    // n-tile 2*bt  -> {r0, r2};  n-tile 2*bt+1 -> {r1, r3}
                    MMA16816(acc[mt][2*bt],   ah[mt], bh[bt][0], bh[bt][2]);
                    MMA16816(acc[mt][2*bt],   ah[mt], bl[bt][0], bl[bt][2]);
                    MMA16816(acc[mt][2*bt],   al[mt], bh[bt][0], bh[bt][2]);
                    MMA16816(acc[mt][2*bt+1], ah[mt], bh[bt][1], bh[bt][3]);
                    MMA16816(acc[mt][2*bt+1], ah[mt], bl[bt][1], bl[bt][3]);
                    MMA16816(acc[mt][2*bt+1], al[mt], bh[bt][1], bh[bt][3]);
                }
            }
        }
        __syncthreads();
        if (c + 2 < NCH) load_chunk_async(st, Ah, Al, Bh, Bl, c + 2, tid);
        CP_COMMIT();
    }
    CP_WAIT0();

    // epilogue: scatter fp32
    const int g = lane >> 2, tig = lane & 3;
#pragma unroll
    for (int mt = 0; mt < 2; mt++) {
#pragma unroll
        for (int nt = 0; nt < 8; nt++) {
            int ng = n0 + warp_n + nt * 8 + tig * 2;
#pragma unroll
            for (int rr = 0; rr < 2; rr++) {
                int m = m0 + warp_m + mt * 16 + g + rr * 8;
                float v0 = acc[mt][nt][rr * 2 + 0];
                float v1 = acc[mt][nt][rr * 2 + 1];
                if (mode == 0) {
                    int b = m >> 11, s = m & (SS - 1);
                    int h = ng >> 6, d0 = ng & 63;
                    float* dst = C + ((size_t)((b * NH + h) * SS + s)) * DKH + d0;
                    dst[0] = v0; dst[1] = v1;
                } else {
                    float* dst = C + (size_t)m * DM + ng;
                    dst[0] = v0; dst[1] = v1;
                }
            }
        }
    }
}

// ---------------- kernel 2: causal flash attention (fp32) -------------------
#define SMEM_FLASH ((4*64*68 + 192) * 4)

__global__ __launch_bounds__(256)
void flash_kernel() {
    extern __shared__ float sm[];
    float* Qt    = sm;
    float* Kt    = sm + 64*68;
    float* Vs    = sm + 2*64*68;
    float* Ps    = sm + 3*64*68;
    float* rowm  = sm + 4*64*68;
    float* rowl  = rowm + 64;
    float* ralpha= rowl + 64;

    const int tid = threadIdx.x;
    const int tx = tid & 15, ty = tid >> 4;
    const int qt = blockIdx.x, h = blockIdx.y, b = blockIdx.z;
    const int q0 = qt * 64;

    const float* Qg = g_Q + ((size_t)(b*NH + h)*SS + q0) * DKH;
    const float* Kg = g_K + ((size_t)(b*NH + h)*SS) * DKH;
    const float* Vg = g_V + ((size_t)(b*NH + h)*SS) * DKH;

#pragma unroll
    for (int r = 0; r < 4; r++) {
        int e = tid + r*256;
        int qq = e >> 4;
        int d4 = (e & 15) << 2;
        float4 v = *(const float4*)(Qg + qq*DKH + d4);
        Qt[(d4+0)*68 + qq] = v.x; Qt[(d4+1)*68 + qq] = v.y;
        Qt[(d4+2)*68 + qq] = v.z; Qt[(d4+3)*68 + qq] = v.w;
    }
    if (tid < 64) { rowm[tid] = -1e30f; rowl[tid] = 0.0f; }

    float o[4][4] = {};

    for (int kt = 0; kt <= qt; kt++) {
        const int k0 = kt * 64;
        __syncthreads();
#pragma unroll
        for (int r = 0; r < 4; r++) {
            int e = tid + r*256;
            int kk = e >> 4;
            int d4 = (e & 15) << 2;
            float4 kv = *(const float4*)(Kg + (size_t)(k0+kk)*DKH + d4);
            Kt[(d4+0)*68 + kk] = kv.x; Kt[(d4+1)*68 + kk] = kv.y;
            Kt[(d4+2)*68 + kk] = kv.z; Kt[(d4+3)*68 + kk] = kv.w;
            float4 vv = *(const float4*)(Vg + (size_t)(k0+kk)*DKH + d4);
            *(float4*)&Vs[kk*68 + d4] = vv;
        }
        __syncthreads();

        float s[4][4] = {};
#pragma unroll 8
        for (int d = 0; d < 64; d++) {
            float4 qv = *(const float4*)&Qt[d*68 + ty*4];
            float4 kv = *(const float4*)&Kt[d*68 + tx*4];
            s[0][0] += qv.x*kv.x; s[0][1] += qv.x*kv.y; s[0][2] += qv.x*kv.z; s[0][3] += qv.x*kv.w;
            s[1][0] += qv.y*kv.x; s[1][1] += qv.y*kv.y; s[1][2] += qv.y*kv.z; s[1][3] += qv.y*kv.w;
            s[2][0] += qv.z*kv.x; s[2][1] += qv.z*kv.y; s[2][2] += qv.z*kv.z; s[2][3] += qv.z*kv.w;
            s[3][0] += qv.w*kv.x; s[3][1] += qv.w*kv.y; s[3][2] += qv.w*kv.z; s[3][3] += qv.w*kv.w;
        }
#pragma unroll
        for (int i = 0; i < 4; i++) {
            int qg = q0 + ty*4 + i;
            float4 pv;
            pv.x = s[i][0]*0.125f + ((k0 + tx*4 + 0) > qg ? -1e9f : 0.0f);
            pv.y = s[i][1]*0.125f + ((k0 + tx*4 + 1) > qg ? -1e9f : 0.0f);
            pv.z = s[i][2]*0.125f + ((k0 + tx*4 + 2) > qg ? -1e9f : 0.0f);
            pv.w = s[i][3]*0.125f + ((k0 + tx*4 + 3) > qg ? -1e9f : 0.0f);
            *(float4*)&Ps[(ty*4+i)*68 + tx*4] = pv;
        }
        __syncthreads();

        if (tid < 64) {
            int row = tid;
            float* pr = &Ps[row*68];
            float mo = rowm[row];
            float mx = mo;
#pragma unroll 8
            for (int j = 0; j < 64; j++) mx = fmaxf(mx, pr[j]);
            float a = __expf(mo - mx);
            float sum = 0.0f;
#pragma unroll 8
            for (int j = 0; j < 64; j++) { float p = __expf(pr[j] - mx); pr[j] = p; sum += p; }
            rowl[row] = rowl[row]*a + sum;
            rowm[row] = mx;
            ralpha[row] = a;
        }
        __syncthreads();

#pragma unroll
        for (int i = 0; i < 4; i++) {
            float a = ralpha[ty*4 + i];
            o[i][0]*=a; o[i][1]*=a; o[i][2]*=a; o[i][3]*=a;
        }
#pragma unroll 8
        for (int kk = 0; kk < 64; kk++) {
            float4 vv = *(const float4*)&Vs[kk*68 + tx*4];
            float p0 = Ps[(ty*4+0)*68 + kk];
            float p1 = Ps[(ty*4+1)*68 + kk];
            float p2 = Ps[(ty*4+2)*68 + kk];
            float p3 = Ps[(ty*4+3)*68 + kk];
            o[0][0]+=p0*vv.x; o[0][1]+=p0*vv.y; o[0][2]+=p0*vv.z; o[0][3]+=p0*vv.w;
            o[1][0]+=p1*vv.x; o[1][1]+=p1*vv.y; o[1][2]+=p1*vv.z; o[1][3]+=p1*vv.w;
            o[2][0]+=p2*vv.x; o[2][1]+=p2*vv.y; o[2][2]+=p2*vv.z; o[2][3]+=p2*vv.w;
            o[3][0]+=p3*vv.x; o[3][1]+=p3*vv.y; o[3][2]+=p3*vv.z; o[3][3]+=p3*vv.w;
        }
    }

#pragma unroll
    for (int i = 0; i < 4; i++) {
        int row = ty*4 + i;
        float inv = 1.0f / rowl[row];
        float4 ov = make_float4(o[i][0]*inv, o[i][1]*inv, o[i][2]*inv, o[i][3]*inv);
        int q = q0 + row;
        *(float4*)(g_A + ((size_t)(b*SS + q))*DM + h*DKH + tx*4) = ov;
    }
}

// ---------------- launch ----------------------------------------------------
extern "C" void kernel_launch(void* const* d_in, const int* in_sizes, int n_in,
                              void* d_out, int out_size) {
    const float* x  = (const float*)d_in[0];
    const float* Wq = (const float*)d_in[2];
    const float* Wk = (const float*)d_in[3];
    const float* Wv = (const float*)d_in[4];
    const float* Wo = (const float*)d_in[5];
    float* out = (float*)d_out;

    static bool attr_done = false;
    if (!attr_done) {
        cudaFuncSetAttribute(tc_gemm_kernel, cudaFuncAttributeMaxDynamicSharedMemorySize, GEMM_SMEM);
        cudaFuncSetAttribute(flash_kernel, cudaFuncAttributeMaxDynamicSharedMemorySize, SMEM_FLASH);
        attr_done = true;
    }

    const int nX4 = MTOT * DM / 4, nW4 = DM * DM / 4;
    convert_kernel<<<(nX4 + 255) / 256, 256>>>(x, 0, nX4);
    convert_kernel<<<(nW4 + 255) / 256, 256>>>(Wq, 1, nW4);
    convert_kernel<<<(nW4 + 255) / 256, 256>>>(Wk, 2, nW4);
    convert_kernel<<<(nW4 + 255) / 256, 256>>>(Wv, 3, nW4);
    convert_kernel<<<(nW4 + 255) / 256, 256>>>(Wo, 4, nW4);

    dim3 gqkv(DM / TNN, MTOT / TMM, 3);
    tc_gemm_kernel<<<gqkv, 256, GEMM_SMEM>>>(nullptr, 0);

    dim3 gflash(SS / 64, NH, BB);
    flash_kernel<<<gflash, 256, SMEM_FLASH>>>();

    convert_kernel<<<(nX4 + 255) / 256, 256>>>(nullptr, 5, nX4);

    dim3 gout(DM / TNN, MTOT / TMM, 1);
    tc_gemm_kernel<<<gout, 256, GEMM_SMEM>>>(out, 1);
}

// round 5
// speedup vs baseline: 2.9106x; 1.8656x over previous
#include <cuda_runtime.h>
#include <cuda_bf16.h>
#include <cstdint>

#define DM 1024
#define NH 16
#define DKH 64
#define BB 2
#define SS 2048
#define MTOT (BB*SS)

// ---------------- scratch (static device arrays: allocation-free) ----------
__device__ __nv_bfloat16 g_Xh[MTOT*DM], g_Xl[MTOT*DM];
__device__ __nv_bfloat16 g_Wh[4*DM*DM], g_Wl[4*DM*DM];
__device__ __nv_bfloat16 g_Qh[MTOT*DM], g_Ql[MTOT*DM];
__device__ __nv_bfloat16 g_Kh[MTOT*DM], g_Kl[MTOT*DM];
__device__ __nv_bfloat16 g_Vh[MTOT*DM], g_Vl[MTOT*DM];
__device__ __nv_bfloat16 g_Ah[MTOT*DM], g_Al[MTOT*DM];

// ---------------- helpers ----------------------------------------------------
__device__ __forceinline__ uint32_t smem_u32(const void* p) {
    uint32_t a;
    asm("{ .reg .u64 t; cvta.to.shared.u64 t, %1; cvt.u32.u64 %0, t; }" : "=r"(a) : "l"(p));
    return a;
}
#define CP_ASYNC16(dst, src) \
    asm volatile("cp.async.cg.shared.global [%0], [%1], 16;" :: "r"(dst), "l"(src))
#define CP_COMMIT()  asm volatile("cp.async.commit_group;" ::: "memory")
#define CP_WAIT1()   asm volatile("cp.async.wait_group 1;" ::: "memory")
#define CP_WAIT0()   asm volatile("cp.async.wait_group 0;" ::: "memory")

#define LDMX4(r0, r1, r2, r3, addr) \
    asm volatile("ldmatrix.sync.aligned.m8n8.x4.shared.b16 {%0,%1,%2,%3}, [%4];" \
        : "=r"(r0), "=r"(r1), "=r"(r2), "=r"(r3) : "r"(addr))
#define LDMX4T(r0, r1, r2, r3, addr) \
    asm volatile("ldmatrix.sync.aligned.m8n8.x4.trans.shared.b16 {%0,%1,%2,%3}, [%4];" \
        : "=r"(r0), "=r"(r1), "=r"(r2), "=r"(r3) : "r"(addr))

#define MMA16816(d, a, b0, b1) \
    asm volatile("mma.sync.aligned.m16n8k16.row.col.f32.bf16.bf16.f32 " \
        "{%0,%1,%2,%3},{%4,%5,%6,%7},{%8,%9},{%0,%1,%2,%3};" \
        : "+f"((d)[0]), "+f"((d)[1]), "+f"((d)[2]), "+f"((d)[3]) \
        : "r"((a)[0]), "r"((a)[1]), "r"((a)[2]), "r"((a)[3]), "r"(b0), "r"(b1))

__device__ __forceinline__ void split2(float a, float b, uint32_t& hi, uint32_t& lo) {
    __nv_bfloat162 h, l;
    h.x = __float2bfloat16(a); h.y = __float2bfloat16(b);
    l.x = __float2bfloat16(a - __bfloat162float(h.x));
    l.y = __float2bfloat16(b - __bfloat162float(h.y));
    hi = *(uint32_t*)&h; lo = *(uint32_t*)&l;
}

// ---------------- convert: fp32 -> bf16 hi/lo (X and weights) ---------------
__global__ __launch_bounds__(256)
void convert_kernel(const float* __restrict__ src, int dst_sel, int n4) {
    int i = blockIdx.x * 256 + threadIdx.x;
    if (i >= n4) return;
    __nv_bfloat16 *h, *l;
    if (dst_sel == 0) { h = g_Xh; l = g_Xl; }
    else { size_t o = (size_t)(dst_sel - 1) * DM * DM; h = g_Wh + o; l = g_Wl + o; }
    float4 v = *(const float4*)(src + (size_t)i * 4);
    uint32_t h0, l0, h1, l1;
    split2(v.x, v.y, h0, l0);
    split2(v.z, v.w, h1, l1);
    *(uint2*)(h + (size_t)i * 4) = make_uint2(h0, h1);
    *(uint2*)(l + (size_t)i * 4) = make_uint2(l0, l1);
}

// ---------------- mma.sync bf16x3 GEMM --------------------------------------
#define TMM 128
#define TNN 128
#define KC 32
#define NCH (DM/KC)            // 32
#define ROWB 80
#define TILE_BYTES (128*ROWB)
#define STAGE_BYTES (4*TILE_BYTES)
#define GEMM_SMEM (2*STAGE_BYTES)

__device__ __forceinline__ void load_chunk_async(uint32_t st,
        const __nv_bfloat16* Ah, const __nv_bfloat16* Al,
        const __nv_bfloat16* Bh, const __nv_bfloat16* Bl, int c, int tid) {
    const __nv_bfloat16* srcs[4] = { Ah, Al, Bh, Bl };
    const int q = tid & 3;
    const int rh = tid >> 2;
#pragma unroll
    for (int t = 0; t < 4; t++) {
        const char* src = (const char*)(srcs[t] + (size_t)c * KC) + q * 16;
#pragma unroll
        for (int rr = 0; rr < 2; rr++) {
            int row = rh + rr * 64;
            uint32_t dst = st + t * TILE_BYTES + row * ROWB + q * 16;
            CP_ASYNC16(dst, src + (size_t)row * (DM * 2));
        }
    }
}

// mode 0: A = X, B = W[z], C = Q/K/V bf16 hi/lo per-head layout
// mode 1: A = attn out (g_Ah/g_Al), B = W[3], C = fp32 out [B,S,D]
__global__ __launch_bounds__(256)
void tc_gemm_kernel(float* __restrict__ Cout, int mode) {
    extern __shared__ char smem[];
    const uint32_t sb = smem_u32(smem);
    const int tid = threadIdx.x, wid = tid >> 5, lane = tid & 31;
    const int n0 = blockIdx.x * TNN, m0 = blockIdx.y * TMM, z = blockIdx.z;

    const int widx = (mode == 0) ? z : 3;
    const __nv_bfloat16* Ah = ((mode == 0) ? g_Xh : g_Ah) + (size_t)m0 * DM;
    const __nv_bfloat16* Al = ((mode == 0) ? g_Xl : g_Al) + (size_t)m0 * DM;
    const __nv_bfloat16* Bh = g_Wh + (size_t)widx * DM * DM + (size_t)n0 * DM;
    const __nv_bfloat16* Bl = g_Wl + (size_t)widx * DM * DM + (size_t)n0 * DM;
    __nv_bfloat16* Ch = (z == 0) ? g_Qh : (z == 1) ? g_Kh : g_Vh;
    __nv_bfloat16* Cl = (z == 0) ? g_Ql : (z == 1) ? g_Kl : g_Vl;

    const int warp_m = (wid & 3) * 32;
    const int warp_n = (wid >> 2) * 64;

    float acc[2][8][4];
#pragma unroll
    for (int i = 0; i < 2; i++)
#pragma unroll
        for (int j = 0; j < 8; j++)
#pragma unroll
            for (int k = 0; k < 4; k++) acc[i][j][k] = 0.0f;

    load_chunk_async(sb, Ah, Al, Bh, Bl, 0, tid); CP_COMMIT();
    load_chunk_async(sb + STAGE_BYTES, Ah, Al, Bh, Bl, 1, tid); CP_COMMIT();

    const int lrow = lane & 15;
    const int lcol = (lane >> 4) * 16;

#pragma unroll 1
    for (int c = 0; c < NCH; c++) {
        CP_WAIT1();
        __syncthreads();
        const uint32_t st = sb + (uint32_t)(c & 1) * STAGE_BYTES;
        const uint32_t aH = st + (warp_m + lrow) * ROWB + lcol;
        const uint32_t aL = aH + TILE_BYTES;
        const uint32_t bH = st + 2 * TILE_BYTES + (warp_n + lrow) * ROWB + lcol;
        const uint32_t bL = bH + TILE_BYTES;

#pragma unroll
        for (int ks = 0; ks < 2; ks++) {
            const int kb = ks * 32;
            uint32_t ah[2][4], al[2][4];
#pragma unroll
            for (int mt = 0; mt < 2; mt++) {
                LDMX4(ah[mt][0], ah[mt][1], ah[mt][2], ah[mt][3], aH + mt * 16 * ROWB + kb);
                LDMX4(al[mt][0], al[mt][1], al[mt][2], al[mt][3], aL + mt * 16 * ROWB + kb);
            }
            uint32_t bh[4][4], bl[4][4];
#pragma unroll
            for (int bt = 0; bt < 4; bt++) {
                LDMX4(bh[bt][0], bh[bt][1], bh[bt][2], bh[bt][3], bH + bt * 16 * ROWB + kb);
                LDMX4(bl[bt][0], bl[bt][1], bl[bt][2], bl[bt][3], bL + bt * 16 * ROWB + kb);
            }
#pragma unroll
            for (int mt = 0; mt < 2; mt++) {
#pragma unroll
                for (int bt = 0; bt < 4; bt++) {
                    MMA16816(acc[mt][2*bt],   ah[mt], bh[bt][0], bh[bt][2]);
                    MMA16816(acc[mt][2*bt],   ah[mt], bl[bt][0], bl[bt][2]);
                    MMA16816(acc[mt][2*bt],   al[mt], bh[bt][0], bh[bt][2]);
                    MMA16816(acc[mt][2*bt+1], ah[mt], bh[bt][1], bh[bt][3]);
                    MMA16816(acc[mt][2*bt+1], ah[mt], bl[bt][1], bl[bt][3]);
                    MMA16816(acc[mt][2*bt+1], al[mt], bh[bt][1], bh[bt][3]);
                }
            }
        }
        __syncthreads();
        if (c + 2 < NCH) load_chunk_async(st, Ah, Al, Bh, Bl, c + 2, tid);
        CP_COMMIT();
    }
    CP_WAIT0();

    const int g = lane >> 2, tig = lane & 3;
#pragma unroll
    for (int mt = 0; mt < 2; mt++) {
#pragma unroll
        for (int nt = 0; nt < 8; nt++) {
            int ng = n0 + warp_n + nt * 8 + tig * 2;
#pragma unroll
            for (int rr = 0; rr < 2; rr++) {
                int m = m0 + warp_m + mt * 16 + g + rr * 8;
                float v0 = acc[mt][nt][rr * 2 + 0];
                float v1 = acc[mt][nt][rr * 2 + 1];
                if (mode == 0) {
                    int b = m >> 11, s = m & (SS - 1);
                    int hh = ng >> 6, d0 = ng & 63;
                    size_t idx = ((size_t)((b * NH + hh) * SS + s)) * DKH + d0;
                    uint32_t hi, lo;
                    split2(v0, v1, hi, lo);
                    *(uint32_t*)(Ch + idx) = hi;
                    *(uint32_t*)(Cl + idx) = lo;
                } else {
                    float* dst = Cout + (size_t)m * DM + ng;
                    dst[0] = v0; dst[1] = v1;
                }
            }
        }
    }
}

// ---------------- flash attention, mma.sync bf16x3 --------------------------
// grid (16, NH, BB), 256 threads; warp w owns q rows [q0+16w, q0+16w+16)
#define BQ 128
#define BK 128
#define FROWB 144                 // 128B data + 16B pad
#define FTILE (128*FROWB)         // 18432
#define FSTAGE (4*FTILE)          // Kh,Kl,Vh,Vl = 73728
#define FLASH_SMEM (2*FSTAGE)     // 147456

__global__ __launch_bounds__(256)
void flash_kernel() {
    extern __shared__ char fsm[];
    const uint32_t sb = smem_u32(fsm);
    const int tid = threadIdx.x, w = tid >> 5, lane = tid & 31;
    const int qt = (int)gridDim.x - 1 - (int)blockIdx.x;
    const int h = blockIdx.y, b = blockIdx.z;
    const int q0 = qt * BQ;
    const int g = lane >> 2, tig = lane & 3;

    const size_t headoff = ((size_t)(b * NH + h) * SS) * DKH;
    const char* Qh_g = (const char*)(g_Qh + headoff + (size_t)q0 * DKH);
    const char* Ql_g = (const char*)(g_Ql + headoff + (size_t)q0 * DKH);
    const char* Kh_g = (const char*)(g_Kh + headoff);
    const char* Kl_g = (const char*)(g_Kl + headoff);
    const char* Vh_g = (const char*)(g_Vh + headoff);
    const char* Vl_g = (const char*)(g_Vl + headoff);

    // ---- stage Q through stage-0 Kh/Kl slots, build Q fragments ----
    {
        const char* srcs[2] = { Qh_g, Ql_g };
#pragma unroll
        for (int t = 0; t < 8; t++) {
            int c = tid + t * 256;
            int tile = c >> 10, row = (c >> 3) & 127, q8 = c & 7;
            uint32_t dst = sb + tile * FTILE + row * FROWB + q8 * 16;
            CP_ASYNC16(dst, srcs[tile] + (size_t)row * 128 + q8 * 16);
        }
    }
    CP_COMMIT(); CP_WAIT0();
    __syncthreads();
    uint32_t qfh[4][4], qfl[4][4];
    {
        uint32_t qbase = sb + (w * 16 + (lane & 15)) * FROWB + (lane >> 4) * 16;
#pragma unroll
        for (int ks = 0; ks < 4; ks++) {
            LDMX4(qfh[ks][0], qfh[ks][1], qfh[ks][2], qfh[ks][3], qbase + ks * 32);
            LDMX4(qfl[ks][0], qfl[ks][1], qfl[ks][2], qfl[ks][3], qbase + FTILE + ks * 32);
        }
    }
    __syncthreads();

    // ---- K/V tile loader ----
    auto load_tile = [&](int kt) {
        const char* srcs[4] = { Kh_g, Kl_g, Vh_g, Vl_g };
        const size_t tile_off = (size_t)kt * BK * 128;   // bytes
        uint32_t stb = sb + (uint32_t)(kt & 1) * FSTAGE;
#pragma unroll
        for (int t = 0; t < 16; t++) {
            int c = tid + t * 256;
            int tile = c >> 10, row = (c >> 3) & 127, q8 = c & 7;
            uint32_t dst = stb + tile * FTILE + row * FROWB + q8 * 16;
            CP_ASYNC16(dst, srcs[tile] + tile_off + (size_t)row * 128 + q8 * 16);
        }
    };
    load_tile(0); CP_COMMIT();
    if (qt >= 1) load_tile(1);
    CP_COMMIT();

    float m0v = -1e30f, m1v = -1e30f, l0v = 0.0f, l1v = 0.0f;
    float o[8][4];
#pragma unroll
    for (int i = 0; i < 8; i++)
#pragma unroll
        for (int j = 0; j < 4; j++) o[i][j] = 0.0f;

#pragma unroll 1
    for (int kt = 0; kt <= qt; kt++) {
        CP_WAIT1();
        __syncthreads();
        const uint32_t st = sb + (uint32_t)(kt & 1) * FSTAGE;

        // ---- S = Q @ K^T ----
        float s[16][4];
#pragma unroll
        for (int i = 0; i < 16; i++)
#pragma unroll
            for (int j = 0; j < 4; j++) s[i][j] = 0.0f;

        const uint32_t kb = st + (lane & 15) * FROWB + (lane >> 4) * 16;
#pragma unroll
        for (int ks = 0; ks < 4; ks++) {
#pragma unroll
            for (int np = 0; np < 8; np++) {
                uint32_t kh[4], kl[4];
                uint32_t addr = kb + np * 16 * FROWB + ks * 32;
                LDMX4(kh[0], kh[1], kh[2], kh[3], addr);
                LDMX4(kl[0], kl[1], kl[2], kl[3], addr + FTILE);
                MMA16816(s[2*np],   qfh[ks], kh[0], kh[2]);
                MMA16816(s[2*np],   qfh[ks], kl[0], kl[2]);
                MMA16816(s[2*np],   qfl[ks], kh[0], kh[2]);
                MMA16816(s[2*np+1], qfh[ks], kh[1], kh[3]);
                MMA16816(s[2*np+1], qfh[ks], kl[1], kl[3]);
                MMA16816(s[2*np+1], qfl[ks], kh[1], kh[3]);
            }
        }

        // ---- scale + causal mask ----
        if (kt == qt) {
            const int rg = 16 * w + g, rg8 = rg + 8;
#pragma unroll
            for (int nt = 0; nt < 16; nt++) {
                int c0 = nt * 8 + 2 * tig, c1 = c0 + 1;
                s[nt][0] = (c0 > rg)  ? -1e9f : s[nt][0] * 0.125f;
                s[nt][1] = (c1 > rg)  ? -1e9f : s[nt][1] * 0.125f;
                s[nt][2] = (c0 > rg8) ? -1e9f : s[nt][2] * 0.125f;
                s[nt][3] = (c1 > rg8) ? -1e9f : s[nt][3] * 0.125f;
            }
        } else {
#pragma unroll
            for (int nt = 0; nt < 16; nt++)
#pragma unroll
                for (int j = 0; j < 4; j++) s[nt][j] *= 0.125f;
        }

        // ---- online softmax (warp-local rows) ----
        float mx0 = -1e30f, mx1 = -1e30f;
#pragma unroll
        for (int nt = 0; nt < 16; nt++) {
            mx0 = fmaxf(mx0, fmaxf(s[nt][0], s[nt][1]));
            mx1 = fmaxf(mx1, fmaxf(s[nt][2], s[nt][3]));
        }
        mx0 = fmaxf(mx0, __shfl_xor_sync(0xffffffffu, mx0, 1));
        mx0 = fmaxf(mx0, __shfl_xor_sync(0xffffffffu, mx0, 2));
        mx1 = fmaxf(mx1, __shfl_xor_sync(0xffffffffu, mx1, 1));
        mx1 = fmaxf(mx1, __shfl_xor_sync(0xffffffffu, mx1, 2));
        float mn0 = fmaxf(m0v, mx0), mn1 = fmaxf(m1v, mx1);
        float a0 = __expf(m0v - mn0), a1 = __expf(m1v - mn1);
        m0v = mn0; m1v = mn1;

        float sum0 = 0.0f, sum1 = 0.0f;
#pragma unroll
        for (int nt = 0; nt < 16; nt++) {
            s[nt][0] = __expf(s[nt][0] - mn0);
            s[nt][1] = __expf(s[nt][1] - mn0);
            s[nt][2] = __expf(s[nt][2] - mn1);
            s[nt][3] = __expf(s[nt][3] - mn1);
            sum0 += s[nt][0] + s[nt][1];
            sum1 += s[nt][2] + s[nt][3];
        }
        sum0 += __shfl_xor_sync(0xffffffffu, sum0, 1);
        sum0 += __shfl_xor_sync(0xffffffffu, sum0, 2);
        sum1 += __shfl_xor_sync(0xffffffffu, sum1, 1);
        sum1 += __shfl_xor_sync(0xffffffffu, sum1, 2);
        l0v = l0v * a0 + sum0;
        l1v = l1v * a1 + sum1;
#pragma unroll
        for (int nt = 0; nt < 8; nt++) {
            o[nt][0] *= a0; o[nt][1] *= a0;
            o[nt][2] *= a1; o[nt][3] *= a1;
        }

        // ---- O += P @ V ----
        const uint32_t vb = st + 2 * FTILE + (lane & 15) * FROWB + (lane >> 4) * 16;
#pragma unroll
        for (int ks2 = 0; ks2 < 8; ks2++) {
            uint32_t pah[4], pal[4];
            split2(s[2*ks2][0],   s[2*ks2][1],   pah[0], pal[0]);
            split2(s[2*ks2][2],   s[2*ks2][3],   pah[1], pal[1]);
            split2(s[2*ks2+1][0], s[2*ks2+1][1], pah[2], pal[2]);
            split2(s[2*ks2+1][2], s[2*ks2+1][3], pah[3], pal[3]);
            uint32_t va = vb + ks2 * 16 * FROWB;
#pragma unroll
            for (int dkp = 0; dkp < 4; dkp++) {
                uint32_t vh[4], vl[4];
                LDMX4T(vh[0], vh[1], vh[2], vh[3], va + dkp * 32);
                LDMX4T(vl[0], vl[1], vl[2], vl[3], va + dkp * 32 + FTILE);
                MMA16816(o[2*dkp],   pah, vh[0], vh[1]);
                MMA16816(o[2*dkp],   pah, vl[0], vl[1]);
                MMA16816(o[2*dkp],   pal, vh[0], vh[1]);
                MMA16816(o[2*dkp+1], pah, vh[2], vh[3]);
                MMA16816(o[2*dkp+1], pah, vl[2], vl[3]);
                MMA16816(o[2*dkp+1], pal, vh[2], vh[3]);
            }
        }

        __syncthreads();
        if (kt + 2 <= qt) load_tile(kt + 2);
        CP_COMMIT();
    }

    // ---- epilogue: O /= l, write bf16 hi/lo to g_Ah/g_Al ----
    const float i0 = 1.0f / l0v, i1 = 1.0f / l1v;
    const int m = q0 + 16 * w + g;
#pragma unroll
    for (int nt = 0; nt < 8; nt++) {
        int col = h * 64 + nt * 8 + 2 * tig;
        size_t i_a = ((size_t)(b * SS + m)) * DM + col;
        size_t i_b = ((size_t)(b * SS + m + 8)) * DM + col;
        uint32_t hi, lo;
        split2(o[nt][0] * i0, o[nt][1] * i0, hi, lo);
        *(uint32_t*)(g_Ah + i_a) = hi;
        *(uint32_t*)(g_Al + i_a) = lo;
        split2(o[nt][2] * i1, o[nt][3] * i1, hi, lo);
        *(uint32_t*)(g_Ah + i_b) = hi;
        *(uint32_t*)(g_Al + i_b) = lo;
    }
}

// ---------------- launch ----------------------------------------------------
extern "C" void kernel_launch(void* const* d_in, const int* in_sizes, int n_in,
                              void* d_out, int out_size) {
    const float* x  = (const float*)d_in[0];
    const float* Wq = (const float*)d_in[2];
    const float* Wk = (const float*)d_in[3];
    const float* Wv = (const float*)d_in[4];
    const float* Wo = (const float*)d_in[5];
    float* out = (float*)d_out;

    static bool attr_done = false;
    if (!attr_done) {
        cudaFuncSetAttribute(tc_gemm_kernel, cudaFuncAttributeMaxDynamicSharedMemorySize, GEMM_SMEM);
        cudaFuncSetAttribute(flash_kernel, cudaFuncAttributeMaxDynamicSharedMemorySize, FLASH_SMEM);
        attr_done = true;
    }

    const int nX4 = MTOT * DM / 4, nW4 = DM * DM / 4;
    convert_kernel<<<(nX4 + 255) / 256, 256>>>(x, 0, nX4);
    convert_kernel<<<(nW4 + 255) / 256, 256>>>(Wq, 1, nW4);
    convert_kernel<<<(nW4 + 255) / 256, 256>>>(Wk, 2, nW4);
    convert_kernel<<<(nW4 + 255) / 256, 256>>>(Wv, 3, nW4);
    convert_kernel<<<(nW4 + 255) / 256, 256>>>(Wo, 4, nW4);

    dim3 gqkv(DM / TNN, MTOT / TMM, 3);
    tc_gemm_kernel<<<gqkv, 256, GEMM_SMEM>>>(nullptr, 0);

    dim3 gflash(SS / BQ, NH, BB);
    flash_kernel<<<gflash, 256, FLASH_SMEM>>>();

    dim3 gout(DM / TNN, MTOT / TMM, 1);
    tc_gemm_kernel<<<gout, 256, GEMM_SMEM>>>(out, 1);
}